// round 9
// baseline (speedup 1.0000x reference)
#include <cuda_runtime.h>
#include <cstdint>
#include <cstddef>

#define B_ 256
#define T_ 2048
#define I_ 128
#define H_ 64
#define G_ 256          // 4*H
#define M_ (B_*T_)      // 524288

// Scratch (device globals: allocation-free rule)
__device__ float g_pre[(size_t)M_ * G_];   // 512 MB
__device__ float g_h0 [(size_t)M_ * H_];   // 128 MB
__device__ float g_h1 [(size_t)M_ * H_];   // 128 MB

// ---------------------------------------------------------------- helpers
__device__ __forceinline__ void mma_tf32(float c[4], const unsigned a[4],
                                         unsigned b0, unsigned b1){
    asm volatile("mma.sync.aligned.m16n8k8.row.col.f32.tf32.tf32.f32 "
        "{%0,%1,%2,%3},{%4,%5,%6,%7},{%8,%9},{%0,%1,%2,%3};"
        : "+f"(c[0]),"+f"(c[1]),"+f"(c[2]),"+f"(c[3])
        : "r"(a[0]),"r"(a[1]),"r"(a[2]),"r"(a[3]),"r"(b0),"r"(b1));
}

__device__ __forceinline__ float tanh_fast(float x){
    float y; asm("tanh.approx.f32 %0, %1;" : "=f"(y) : "f"(x)); return y;
}

__device__ __forceinline__ unsigned smaddr(const void* p){
    return (unsigned)__cvta_generic_to_shared(p);
}
__device__ __forceinline__ void cp16(unsigned dst, const void* src){
    asm volatile("cp.async.cg.shared.global [%0], [%1], 16;" :: "r"(dst), "l"(src));
}

// ---------------------------------------------------------------- pre-GEMM
// (R8 exact) 512 threads, BM=128, N=256, K chunked 32, cp.async dbl buffer.
#define KC 32
#define KP 36
#define STAGE_F (128*KP + 256*KP)

template<int K>
__global__ void __launch_bounds__(512,1)
gemm_pre(const float* __restrict__ A, const float* __restrict__ W,
         const float* __restrict__ b_ih, const float* __restrict__ b_hh,
         float* __restrict__ out)
{
    extern __shared__ float sm[];
    float* bs = sm + 2*STAGE_F;

    const int tid = threadIdx.x;
    const size_t m0 = (size_t)blockIdx.x * 128;

    if (tid < 256) bs[tid] = b_ih[tid] + b_hh[tid];

    auto copy_chunk = [&](int c, int st){
        float* Asd = sm + st*STAGE_F;
        float* Wsd = Asd + 128*KP;
        #pragma unroll
        for (int i = tid; i < 128*8; i += 512){
            int row = i >> 3, seg = i & 7;
            cp16(smaddr(Asd + row*KP + seg*4),
                 A + (m0 + row)*(size_t)K + c*KC + seg*4);
        }
        #pragma unroll
        for (int i = tid; i < 256*8; i += 512){
            int row = i >> 3, seg = i & 7;
            cp16(smaddr(Wsd + row*KP + seg*4),
                 W + (size_t)row*K + c*KC + seg*4);
        }
    };

    const int warp = tid >> 5, lane = tid & 31;
    const int wm = warp >> 2, wn = warp & 3;
    const int gid = lane >> 2, tig = lane & 3;

    float acc[2][8][4];
    #pragma unroll
    for (int a = 0; a < 2; a++)
        #pragma unroll
        for (int b = 0; b < 8; b++)
            #pragma unroll
            for (int d = 0; d < 4; d++) acc[a][b][d] = 0.f;

    constexpr int NCH = K / KC;

    copy_chunk(0, 0);
    asm volatile("cp.async.commit_group;");

    for (int c = 0; c < NCH; ++c){
        if (c + 1 < NCH){
            copy_chunk(c + 1, (c + 1) & 1);
            asm volatile("cp.async.commit_group;");
            asm volatile("cp.async.wait_group 1;");
        } else {
            asm volatile("cp.async.wait_group 0;");
        }
        __syncthreads();

        const float* As = sm + (c & 1)*STAGE_F;
        const float* Ws = As + 128*KP;

        #pragma unroll
        for (int ks = 0; ks < KC/8; ++ks){
            const int cc = ks*8 + tig;
            unsigned af[2][4];
            #pragma unroll
            for (int mt = 0; mt < 2; mt++){
                int r = wm*32 + mt*16 + gid;
                af[mt][0] = __float_as_uint(As[r*KP + cc]);
                af[mt][1] = __float_as_uint(As[(r+8)*KP + cc]);
                af[mt][2] = __float_as_uint(As[r*KP + cc + 4]);
                af[mt][3] = __float_as_uint(As[(r+8)*KP + cc + 4]);
            }
            #pragma unroll
            for (int nt = 0; nt < 8; nt++){
                int n = wn*64 + nt*8 + gid;
                unsigned b0 = __float_as_uint(Ws[n*KP + cc]);
                unsigned b1 = __float_as_uint(Ws[n*KP + cc + 4]);
                mma_tf32(acc[0][nt], af[0], b0, b1);
                mma_tf32(acc[1][nt], af[1], b0, b1);
            }
        }
        __syncthreads();
    }

    #pragma unroll
    for (int mt = 0; mt < 2; mt++){
        size_t r = m0 + wm*32 + mt*16 + gid;
        #pragma unroll
        for (int nt = 0; nt < 8; nt++){
            int col = wn*64 + nt*8 + 2*tig;
            float bb0 = bs[col], bb1 = bs[col+1];
            *(float2*)(out + r*G_ + col)
                = make_float2(acc[mt][nt][0] + bb0, acc[mt][nt][1] + bb1);
            *(float2*)(out + (r+8)*G_ + col)
                = make_float2(acc[mt][nt][2] + bb0, acc[mt][nt][3] + bb1);
        }
    }
}

// ---------------------------------------------------------------- LSTM scan
// Block = TWO sequences, 256 threads; grid 128 <= 148 SMs -> one wave, no
// 2-block contention. tid -> (j = tid>>2, gt = tid&3). The SAME 32 K-paired
// weight u64 regs serve both sequences through separate accumulator chains
// (no duplication). Gates exchanged via shfl within the 4-lane cell group;
// ONE barrier/step; h_s double-buffered; tanh.approx activations
// (sigma(x) = 0.5*tanh(0.5x)+0.5). Cell states in registers.
__global__ void __launch_bounds__(256,2)
lstm_scan(const float* __restrict__ pre, const float* __restrict__ w_hh,
          float* __restrict__ h_out)
{
    __shared__ __align__(16) float h_s[2][2][H_];   // [buf][seq][j]

    const int tid = threadIdx.x;
    const int j   = tid >> 2;          // cell 0..63
    const int gt  = tid & 3;           // 0=i 1=f 2=g 3=o
    const int grow = gt * H_ + j;      // row in w_hh / column in pre
    const int b0  = blockIdx.x * 2;

    // activation: gt==2 -> tanh(a); else sigmoid(a) = 0.5*tanh(0.5a)+0.5
    const float am = (gt == 2) ? 1.f : 0.5f;
    const float ab = (gt == 2) ? 0.f : 0.5f;

    if (tid < 2*2*H_) ((float*)h_s)[tid] = 0.f;

    // 32 K-paired weight u64: wpk[m] = {w[2m], w[2m+1]}
    unsigned long long wpk[32];
    {
        const float4* wr = (const float4*)(w_hh + grow*H_);
        #pragma unroll
        for (int k4 = 0; k4 < 16; k4++){
            float4 v = wr[k4];
            asm("mov.b64 %0,{%1,%2};" : "=l"(wpk[2*k4+0]) : "f"(v.x), "f"(v.y));
            asm("mov.b64 %0,{%1,%2};" : "=l"(wpk[2*k4+1]) : "f"(v.z), "f"(v.w));
        }
    }

    // pre pointers + distance-2 prefetch, both sequences
    const float* ppA = pre + ((size_t)b0     * T_) * G_ + grow;
    const float* ppB = pre + ((size_t)(b0+1) * T_) * G_ + grow;
    float pA0 = ppA[0],  pB0 = ppB[0];
    float pA1 = ppA[G_], pB1 = ppB[G_];

    float cregA = 0.f, cregB = 0.f;
    const unsigned lbase = (tid & 31) & ~3u;

    __syncthreads();

    for (int t = 0; t < T_; ++t){
        int tp = (t + 2 < T_) ? t + 2 : T_ - 1;
        float pAn = __ldg(ppA + (size_t)tp * G_);
        float pBn = __ldg(ppB + (size_t)tp * G_);

        const int rb = t & 1;

        // ---- seq A matvec: 32 FFMA2, 4 chains of 8
        unsigned long long a0, a1, a2, a3;
        asm("mov.b64 %0,{%1,%2};" : "=l"(a0) : "f"(pA0), "f"(0.f));
        asm("mov.b64 %0,{%1,%2};" : "=l"(a1) : "f"(0.f), "f"(0.f));
        asm("mov.b64 %0,{%1,%2};" : "=l"(a2) : "f"(0.f), "f"(0.f));
        asm("mov.b64 %0,{%1,%2};" : "=l"(a3) : "f"(0.f), "f"(0.f));
        // ---- seq B matvec: same weights, separate chains
        unsigned long long b0c, b1c, b2c, b3c;
        asm("mov.b64 %0,{%1,%2};" : "=l"(b0c) : "f"(pB0), "f"(0.f));
        asm("mov.b64 %0,{%1,%2};" : "=l"(b1c) : "f"(0.f), "f"(0.f));
        asm("mov.b64 %0,{%1,%2};" : "=l"(b2c) : "f"(0.f), "f"(0.f));
        asm("mov.b64 %0,{%1,%2};" : "=l"(b3c) : "f"(0.f), "f"(0.f));

        const ulonglong2* hvA = (const ulonglong2*)h_s[rb][0];
        const ulonglong2* hvB = (const ulonglong2*)h_s[rb][1];
        #pragma unroll
        for (int i = 0; i < 8; i++){
            ulonglong2 xA = hvA[i];
            ulonglong2 yA = hvA[i+8];
            ulonglong2 xB = hvB[i];
            ulonglong2 yB = hvB[i+8];
            asm("fma.rn.f32x2 %0, %1, %2, %0;" : "+l"(a0)  : "l"(wpk[2*i+0]),  "l"(xA.x));
            asm("fma.rn.f32x2 %0, %1, %2, %0;" : "+l"(a1)  : "l"(wpk[2*i+1]),  "l"(xA.y));
            asm("fma.rn.f32x2 %0, %1, %2, %0;" : "+l"(a2)  : "l"(wpk[2*i+16]), "l"(yA.x));
            asm("fma.rn.f32x2 %0, %1, %2, %0;" : "+l"(a3)  : "l"(wpk[2*i+17]), "l"(yA.y));
            asm("fma.rn.f32x2 %0, %1, %2, %0;" : "+l"(b0c) : "l"(wpk[2*i+0]),  "l"(xB.x));
            asm("fma.rn.f32x2 %0, %1, %2, %0;" : "+l"(b1c) : "l"(wpk[2*i+1]),  "l"(xB.y));
            asm("fma.rn.f32x2 %0, %1, %2, %0;" : "+l"(b2c) : "l"(wpk[2*i+16]), "l"(yB.x));
            asm("fma.rn.f32x2 %0, %1, %2, %0;" : "+l"(b3c) : "l"(wpk[2*i+17]), "l"(yB.y));
        }

        unsigned long long sA, sB, u, v2;
        asm("add.rn.f32x2 %0, %1, %2;" : "=l"(u)  : "l"(a0), "l"(a1));
        asm("add.rn.f32x2 %0, %1, %2;" : "=l"(v2) : "l"(a2), "l"(a3));
        asm("add.rn.f32x2 %0, %1, %2;" : "=l"(sA) : "l"(u),  "l"(v2));
        asm("add.rn.f32x2 %0, %1, %2;" : "=l"(u)  : "l"(b0c), "l"(b1c));
        asm("add.rn.f32x2 %0, %1, %2;" : "=l"(v2) : "l"(b2c), "l"(b3c));
        asm("add.rn.f32x2 %0, %1, %2;" : "=l"(sB) : "l"(u),   "l"(v2));
        float al, ah, bl, bh;
        asm("mov.b64 {%0,%1}, %2;" : "=f"(al), "=f"(ah) : "l"(sA));
        asm("mov.b64 {%0,%1}, %2;" : "=f"(bl), "=f"(bh) : "l"(sB));
        float aA = al + ah;    // seq A gate pre-activation
        float aB = bl + bh;    // seq B

        float vA = fmaf(tanh_fast(aA * am), 2.f*am, ab) - ab*0.f;  // see below
        // note: sigma(x)=0.5*tanh(0.5x)+0.5 -> v = tanh(a*am)*am' + ab with
        // am'=0.5 for sigmoid, 1 for tanh. am carries the arg scale; reuse:
        vA = fmaf(tanh_fast(aA * am), (gt==2)?1.f:0.5f, ab);
        float vB = fmaf(tanh_fast(aB * am), (gt==2)?1.f:0.5f, ab);

        // gather 4 gates of cell j (both seqs)
        float ivA = __shfl_sync(0xffffffffu, vA, lbase + 0, 32);
        float fvA = __shfl_sync(0xffffffffu, vA, lbase + 1, 32);
        float gvA = __shfl_sync(0xffffffffu, vA, lbase + 2, 32);
        float ovA = __shfl_sync(0xffffffffu, vA, lbase + 3, 32);
        float ivB = __shfl_sync(0xffffffffu, vB, lbase + 0, 32);
        float fvB = __shfl_sync(0xffffffffu, vB, lbase + 1, 32);
        float gvB = __shfl_sync(0xffffffffu, vB, lbase + 2, 32);
        float ovB = __shfl_sync(0xffffffffu, vB, lbase + 3, 32);

        cregA = fmaf(fvA, cregA, ivA * gvA);
        cregB = fmaf(fvB, cregB, ivB * gvB);
        float hA = ovA * tanh_fast(cregA);
        float hB = ovB * tanh_fast(cregB);

        if (gt == 0){
            h_s[rb ^ 1][0][j] = hA;
            h_s[rb ^ 1][1][j] = hB;
            h_out[((size_t)b0     * T_ + t) * H_ + j] = hA;
            h_out[((size_t)(b0+1) * T_ + t) * H_ + j] = hB;
        }
        pA0 = pA1; pA1 = pAn;
        pB0 = pB1; pB1 = pBn;
        __syncthreads();
    }
}

// ---------------------------------------------------------------- FC head
__global__ void fc_kernel(const float* __restrict__ h, const float* __restrict__ fw,
                          const float* __restrict__ fb, float* __restrict__ out)
{
    size_t m = (size_t)blockIdx.x * blockDim.x + threadIdx.x;
    const float4* hv = (const float4*)(h + m * H_);
    float acc = 0.f;
    #pragma unroll
    for (int i = 0; i < H_/4; i++){
        float4 a = hv[i];
        float4 w = __ldg(((const float4*)fw) + i);
        acc = fmaf(a.x, w.x, fmaf(a.y, w.y, fmaf(a.z, w.z, fmaf(a.w, w.w, acc))));
    }
    out[m] = acc + __ldg(fb);
}

// ---------------------------------------------------------------- launch
extern "C" void kernel_launch(void* const* d_in, const int* in_sizes, int n_in,
                              void* d_out, int out_size)
{
    const float* x     = (const float*)d_in[0];
    const float* w_ih0 = (const float*)d_in[1];
    const float* w_hh0 = (const float*)d_in[2];
    const float* b_ih0 = (const float*)d_in[3];
    const float* b_hh0 = (const float*)d_in[4];
    const float* w_ih1 = (const float*)d_in[5];
    const float* w_hh1 = (const float*)d_in[6];
    const float* b_ih1 = (const float*)d_in[7];
    const float* b_hh1 = (const float*)d_in[8];
    const float* w_ih2 = (const float*)d_in[9];
    const float* w_hh2 = (const float*)d_in[10];
    const float* b_ih2 = (const float*)d_in[11];
    const float* b_hh2 = (const float*)d_in[12];
    const float* fc_w  = (const float*)d_in[13];
    const float* fc_b  = (const float*)d_in[14];
    float* out = (float*)d_out;

    float *pre, *h0, *h1;
    cudaGetSymbolAddress((void**)&pre, g_pre);
    cudaGetSymbolAddress((void**)&h0,  g_h0);
    cudaGetSymbolAddress((void**)&h1,  g_h1);

    const int smemG = (2*STAGE_F + 256) * 4;
    cudaFuncSetAttribute(gemm_pre<128>, cudaFuncAttributeMaxDynamicSharedMemorySize, smemG);
    cudaFuncSetAttribute(gemm_pre<64>,  cudaFuncAttributeMaxDynamicSharedMemorySize, smemG);

    gemm_pre<128><<<M_/128, 512, smemG>>>(x,  w_ih0, b_ih0, b_hh0, pre);
    lstm_scan    <<<B_/2,   256>>>(pre, w_hh0, h0);
    gemm_pre<64> <<<M_/128, 512, smemG>>>(h0, w_ih1, b_ih1, b_hh1, pre);
    lstm_scan    <<<B_/2,   256>>>(pre, w_hh1, h1);
    gemm_pre<64> <<<M_/128, 512, smemG>>>(h1, w_ih2, b_ih2, b_hh2, pre);
    lstm_scan    <<<B_/2,   256>>>(pre, w_hh2, h0);
    fc_kernel    <<<M_/256, 256>>>(h0, fc_w, fc_b, out);
}

// round 10
// speedup vs baseline: 1.2900x; 1.2900x over previous
#include <cuda_runtime.h>
#include <cstdint>
#include <cstddef>

#define B_ 256
#define T_ 2048
#define I_ 128
#define H_ 64
#define G_ 256          // 4*H
#define M_ (B_*T_)      // 524288

// Scratch (device globals: allocation-free rule)
__device__ float g_pre[(size_t)M_ * G_];   // 512 MB
__device__ float g_h0 [(size_t)M_ * H_];   // 128 MB
__device__ float g_h1 [(size_t)M_ * H_];   // 128 MB

// ---------------------------------------------------------------- helpers
__device__ __forceinline__ void mma_tf32(float c[4], const unsigned a[4],
                                         unsigned b0, unsigned b1){
    asm volatile("mma.sync.aligned.m16n8k8.row.col.f32.tf32.tf32.f32 "
        "{%0,%1,%2,%3},{%4,%5,%6,%7},{%8,%9},{%0,%1,%2,%3};"
        : "+f"(c[0]),"+f"(c[1]),"+f"(c[2]),"+f"(c[3])
        : "r"(a[0]),"r"(a[1]),"r"(a[2]),"r"(a[3]),"r"(b0),"r"(b1));
}

__device__ __forceinline__ float tanh_fast(float x){
    float y; asm("tanh.approx.f32 %0, %1;" : "=f"(y) : "f"(x)); return y;
}

__device__ __forceinline__ unsigned smaddr(const void* p){
    return (unsigned)__cvta_generic_to_shared(p);
}
__device__ __forceinline__ void cp16(unsigned dst, const void* src){
    asm volatile("cp.async.cg.shared.global [%0], [%1], 16;" :: "r"(dst), "l"(src));
}

// ---------------------------------------------------------------- pre-GEMM
// (R8 exact) 512 threads, BM=128, N=256, K chunked 32, cp.async dbl buffer.
#define KC 32
#define KP 36
#define STAGE_F (128*KP + 256*KP)

template<int K>
__global__ void __launch_bounds__(512,1)
gemm_pre(const float* __restrict__ A, const float* __restrict__ W,
         const float* __restrict__ b_ih, const float* __restrict__ b_hh,
         float* __restrict__ out)
{
    extern __shared__ float sm[];
    float* bs = sm + 2*STAGE_F;

    const int tid = threadIdx.x;
    const size_t m0 = (size_t)blockIdx.x * 128;

    if (tid < 256) bs[tid] = b_ih[tid] + b_hh[tid];

    auto copy_chunk = [&](int c, int st){
        float* Asd = sm + st*STAGE_F;
        float* Wsd = Asd + 128*KP;
        #pragma unroll
        for (int i = tid; i < 128*8; i += 512){
            int row = i >> 3, seg = i & 7;
            cp16(smaddr(Asd + row*KP + seg*4),
                 A + (m0 + row)*(size_t)K + c*KC + seg*4);
        }
        #pragma unroll
        for (int i = tid; i < 256*8; i += 512){
            int row = i >> 3, seg = i & 7;
            cp16(smaddr(Wsd + row*KP + seg*4),
                 W + (size_t)row*K + c*KC + seg*4);
        }
    };

    const int warp = tid >> 5, lane = tid & 31;
    const int wm = warp >> 2, wn = warp & 3;
    const int gid = lane >> 2, tig = lane & 3;

    float acc[2][8][4];
    #pragma unroll
    for (int a = 0; a < 2; a++)
        #pragma unroll
        for (int b = 0; b < 8; b++)
            #pragma unroll
            for (int d = 0; d < 4; d++) acc[a][b][d] = 0.f;

    constexpr int NCH = K / KC;

    copy_chunk(0, 0);
    asm volatile("cp.async.commit_group;");

    for (int c = 0; c < NCH; ++c){
        if (c + 1 < NCH){
            copy_chunk(c + 1, (c + 1) & 1);
            asm volatile("cp.async.commit_group;");
            asm volatile("cp.async.wait_group 1;");
        } else {
            asm volatile("cp.async.wait_group 0;");
        }
        __syncthreads();

        const float* As = sm + (c & 1)*STAGE_F;
        const float* Ws = As + 128*KP;

        #pragma unroll
        for (int ks = 0; ks < KC/8; ++ks){
            const int cc = ks*8 + tig;
            unsigned af[2][4];
            #pragma unroll
            for (int mt = 0; mt < 2; mt++){
                int r = wm*32 + mt*16 + gid;
                af[mt][0] = __float_as_uint(As[r*KP + cc]);
                af[mt][1] = __float_as_uint(As[(r+8)*KP + cc]);
                af[mt][2] = __float_as_uint(As[r*KP + cc + 4]);
                af[mt][3] = __float_as_uint(As[(r+8)*KP + cc + 4]);
            }
            #pragma unroll
            for (int nt = 0; nt < 8; nt++){
                int n = wn*64 + nt*8 + gid;
                unsigned b0 = __float_as_uint(Ws[n*KP + cc]);
                unsigned b1 = __float_as_uint(Ws[n*KP + cc + 4]);
                mma_tf32(acc[0][nt], af[0], b0, b1);
                mma_tf32(acc[1][nt], af[1], b0, b1);
            }
        }
        __syncthreads();
    }

    #pragma unroll
    for (int mt = 0; mt < 2; mt++){
        size_t r = m0 + wm*32 + mt*16 + gid;
        #pragma unroll
        for (int nt = 0; nt < 8; nt++){
            int col = wn*64 + nt*8 + 2*tig;
            float bb0 = bs[col], bb1 = bs[col+1];
            *(float2*)(out + r*G_ + col)
                = make_float2(acc[mt][nt][0] + bb0, acc[mt][nt][1] + bb1);
            *(float2*)(out + (r+8)*G_ + col)
                = make_float2(acc[mt][nt][2] + bb0, acc[mt][nt][3] + bb1);
        }
    }
}

// ---------------------------------------------------------------- LSTM scan
// Block = TWO sequences in two independent 256-thread halves (warps 0-7 seq
// A, warps 8-15 seq B); each half is exactly the R6 layout: st = tid&255 ->
// (j = st>>2, gt = st&3), 4 gates of a cell in 4 adjacent lanes, gate
// exchange via shfl, K-paired weights in 32 u64 regs, per-warp broadcast
// LDS of the half's own h buffer, ONE barrier/step, double-buffered h_s,
// tanh.approx activations. Grid 128 -> 1 block/SM, 4 warps/SMSP.
__global__ void __launch_bounds__(512,1)
lstm_scan(const float* __restrict__ pre, const float* __restrict__ w_hh,
          float* __restrict__ h_out)
{
    __shared__ __align__(16) float h_s[2][2][H_];   // [buf][seq][j]

    const int tid = threadIdx.x;
    const int sh  = tid >> 8;          // seq half 0/1
    const int st  = tid & 255;         // thread-in-half
    const int j   = st >> 2;           // cell 0..63
    const int gt  = st & 3;            // 0=i 1=f 2=g 3=o
    const int grow = gt * H_ + j;      // row in w_hh / column in pre
    const int b   = blockIdx.x * 2 + sh;

    // activation: gt==2 -> tanh(a); else sigmoid(a) = 0.5*tanh(0.5a)+0.5
    const float am = (gt == 2) ? 1.f : 0.5f;
    const float ab = (gt == 2) ? 0.f : 0.5f;

    if (tid < 2*2*H_) ((float*)h_s)[tid] = 0.f;

    // 32 K-paired weight u64: wpk[m] = {w[2m], w[2m+1]}
    unsigned long long wpk[32];
    {
        const float4* wr = (const float4*)(w_hh + grow*H_);
        #pragma unroll
        for (int k4 = 0; k4 < 16; k4++){
            float4 v = wr[k4];
            asm("mov.b64 %0,{%1,%2};" : "=l"(wpk[2*k4+0]) : "f"(v.x), "f"(v.y));
            asm("mov.b64 %0,{%1,%2};" : "=l"(wpk[2*k4+1]) : "f"(v.z), "f"(v.w));
        }
    }

    // pre pointer + distance-2 prefetch
    const float* pp = pre + ((size_t)b * T_) * G_ + grow;
    float p0 = pp[0];
    float p1 = pp[G_];

    float creg = 0.f;
    const unsigned lbase = (tid & 31) & ~3u;

    __syncthreads();

    for (int t = 0; t < T_; ++t){
        int tp = (t + 2 < T_) ? t + 2 : T_ - 1;
        float pn = __ldg(pp + (size_t)tp * G_);

        const int rb = t & 1;
        unsigned long long a0, a1, a2, a3;
        asm("mov.b64 %0,{%1,%2};" : "=l"(a0) : "f"(p0),  "f"(0.f));
        asm("mov.b64 %0,{%1,%2};" : "=l"(a1) : "f"(0.f), "f"(0.f));
        asm("mov.b64 %0,{%1,%2};" : "=l"(a2) : "f"(0.f), "f"(0.f));
        asm("mov.b64 %0,{%1,%2};" : "=l"(a3) : "f"(0.f), "f"(0.f));

        const ulonglong2* hv = (const ulonglong2*)h_s[rb][sh];
        #pragma unroll
        for (int i = 0; i < 8; i++){
            ulonglong2 x = hv[i];
            ulonglong2 y = hv[i+8];
            asm("fma.rn.f32x2 %0, %1, %2, %0;" : "+l"(a0) : "l"(wpk[2*i+0]),  "l"(x.x));
            asm("fma.rn.f32x2 %0, %1, %2, %0;" : "+l"(a1) : "l"(wpk[2*i+1]),  "l"(x.y));
            asm("fma.rn.f32x2 %0, %1, %2, %0;" : "+l"(a2) : "l"(wpk[2*i+16]), "l"(y.x));
            asm("fma.rn.f32x2 %0, %1, %2, %0;" : "+l"(a3) : "l"(wpk[2*i+17]), "l"(y.y));
        }
        unsigned long long s01, s23, s;
        asm("add.rn.f32x2 %0, %1, %2;" : "=l"(s01) : "l"(a0), "l"(a1));
        asm("add.rn.f32x2 %0, %1, %2;" : "=l"(s23) : "l"(a2), "l"(a3));
        asm("add.rn.f32x2 %0, %1, %2;" : "=l"(s)   : "l"(s01), "l"(s23));
        float sl, shi;
        asm("mov.b64 {%0,%1}, %2;" : "=f"(sl), "=f"(shi) : "l"(s));
        float a = sl + shi;                        // gate pre-activation

        // activation via single MUFU tanh
        float v = fmaf(tanh_fast(a * am), (gt == 2) ? 1.f : 0.5f, ab);

        float iv = __shfl_sync(0xffffffffu, v, lbase + 0, 32);
        float fv = __shfl_sync(0xffffffffu, v, lbase + 1, 32);
        float gv = __shfl_sync(0xffffffffu, v, lbase + 2, 32);
        float ov = __shfl_sync(0xffffffffu, v, lbase + 3, 32);

        creg = fmaf(fv, creg, iv * gv);
        float h = ov * tanh_fast(creg);

        if (gt == 0){
            h_s[rb ^ 1][sh][j] = h;
            h_out[((size_t)b * T_ + t) * H_ + j] = h;
        }
        p0 = p1; p1 = pn;
        __syncthreads();
    }
}

// ---------------------------------------------------------------- FC head
__global__ void fc_kernel(const float* __restrict__ h, const float* __restrict__ fw,
                          const float* __restrict__ fb, float* __restrict__ out)
{
    size_t m = (size_t)blockIdx.x * blockDim.x + threadIdx.x;
    const float4* hv = (const float4*)(h + m * H_);
    float acc = 0.f;
    #pragma unroll
    for (int i = 0; i < H_/4; i++){
        float4 a = hv[i];
        float4 w = __ldg(((const float4*)fw) + i);
        acc = fmaf(a.x, w.x, fmaf(a.y, w.y, fmaf(a.z, w.z, fmaf(a.w, w.w, acc))));
    }
    out[m] = acc + __ldg(fb);
}

// ---------------------------------------------------------------- launch
extern "C" void kernel_launch(void* const* d_in, const int* in_sizes, int n_in,
                              void* d_out, int out_size)
{
    const float* x     = (const float*)d_in[0];
    const float* w_ih0 = (const float*)d_in[1];
    const float* w_hh0 = (const float*)d_in[2];
    const float* b_ih0 = (const float*)d_in[3];
    const float* b_hh0 = (const float*)d_in[4];
    const float* w_ih1 = (const float*)d_in[5];
    const float* w_hh1 = (const float*)d_in[6];
    const float* b_ih1 = (const float*)d_in[7];
    const float* b_hh1 = (const float*)d_in[8];
    const float* w_ih2 = (const float*)d_in[9];
    const float* w_hh2 = (const float*)d_in[10];
    const float* b_ih2 = (const float*)d_in[11];
    const float* b_hh2 = (const float*)d_in[12];
    const float* fc_w  = (const float*)d_in[13];
    const float* fc_b  = (const float*)d_in[14];
    float* out = (float*)d_out;

    float *pre, *h0, *h1;
    cudaGetSymbolAddress((void**)&pre, g_pre);
    cudaGetSymbolAddress((void**)&h0,  g_h0);
    cudaGetSymbolAddress((void**)&h1,  g_h1);

    const int smemG = (2*STAGE_F + 256) * 4;
    cudaFuncSetAttribute(gemm_pre<128>, cudaFuncAttributeMaxDynamicSharedMemorySize, smemG);
    cudaFuncSetAttribute(gemm_pre<64>,  cudaFuncAttributeMaxDynamicSharedMemorySize, smemG);

    gemm_pre<128><<<M_/128, 512, smemG>>>(x,  w_ih0, b_ih0, b_hh0, pre);
    lstm_scan    <<<B_/2,   512>>>(pre, w_hh0, h0);
    gemm_pre<64> <<<M_/128, 512, smemG>>>(h0, w_ih1, b_ih1, b_hh1, pre);
    lstm_scan    <<<B_/2,   512>>>(pre, w_hh1, h1);
    gemm_pre<64> <<<M_/128, 512, smemG>>>(h1, w_ih2, b_ih2, b_hh2, pre);
    lstm_scan    <<<B_/2,   512>>>(pre, w_hh2, h0);
    fc_kernel    <<<M_/256, 256>>>(h0, fc_w, fc_b, out);
}